// round 14
// baseline (speedup 1.0000x reference)
#include <cuda_runtime.h>
#include <math.h>

#define B_  16
#define C_  256
#define H_  96
#define W_  96
#define G_  4
#define KK  3
#define RED 4
#define CH  (C_ / RED)        // 64
#define PLANE (H_ * W_)       // 9216
#define BC (B_ * C_)          // 4096

// Scratch (allocation-free rule -> __device__ globals)
__device__ float g_pooled[B_ * C_ * 9];
__device__ float g_gmean [B_ * C_];
__device__ float g_weight[B_ * C_ * 9];
__device__ float g_bias  [B_ * C_];
__device__ float g_w1t[C_ * CH];        // w1t[k][o] = w1[o][k]   (256 x 64)
__device__ float g_w2t[CH * C_ * G_];   // w2t[k][gc] = w2[gc][k] (64 x 1024)

// ---------------------------------------------------------------------------
// Kernel 1: pool (blocks 0..4095): 9 warps, one warp per 32x32 pooling block.
// Blocks 4096..4175: weight transpose. Pool's x reads use DEFAULT policy:
// they seed the L2 window that conv consumes in reverse.
// ---------------------------------------------------------------------------
__global__ __launch_bounds__(288) void pool_kernel(const float* __restrict__ x,
                                                   const float* __restrict__ w1,
                                                   const float* __restrict__ w2)
{
    int tid = threadIdx.x;
    if (blockIdx.x >= BC) {
        int idx = (blockIdx.x - BC) * 288 + tid;
        if (idx < C_ * CH) {
            int k = idx / CH, o = idx % CH;
            g_w1t[idx] = w1[o * C_ + k];
        }
        for (int i = idx; i < CH * C_ * G_; i += 80 * 288) {
            int k = i / (C_ * G_), gc = i % (C_ * G_);
            g_w2t[i] = w2[gc * CH + k];
        }
        return;
    }

    int bc = blockIdx.x;
    const float4* xp = reinterpret_cast<const float4*>(x + (size_t)bc * PLANE);
    __shared__ float bins[9];
    int wid = tid >> 5, lane = tid & 31;
    int br = wid / 3, cb = wid % 3;   // pooling block (row, col)

    float a = 0.f;
    #pragma unroll
    for (int j = 0; j < 8; j++) {
        int idx = j * 32 + lane;
        int r = idx >> 3, c = idx & 7;           // 8 float4 per block row
        float4 v = xp[(br * 32 + r) * 24 + cb * 8 + c];
        a += (v.x + v.y) + (v.z + v.w);
    }
    #pragma unroll
    for (int o = 16; o > 0; o >>= 1) a += __shfl_down_sync(0xffffffffu, a, o);
    if (lane == 0) bins[wid] = a;
    __syncthreads();

    if (tid < 9) g_pooled[bc * 9 + tid] = bins[tid] * (1.f / 1024.f);
    if (tid == 0) {
        float t = 0.f;
        #pragma unroll
        for (int i = 0; i < 9; i++) t += bins[i];
        g_gmean[bc] = t * (1.f / (float)PLANE);
    }
}

// ---------------------------------------------------------------------------
// Kernel 2: proj + softmax + mixdown. PDL completion ordering.
// ---------------------------------------------------------------------------
__global__ __launch_bounds__(256) void proj_kernel(
    const float* __restrict__ b1,
    const float* __restrict__ bn_g, const float* __restrict__ bn_b,
    const float* __restrict__ bn_m, const float* __restrict__ bn_v,
    const float* __restrict__ b2,
    const float* __restrict__ w_k, const float* __restrict__ b_k)
{
    int pos = blockIdx.x;
    int b   = blockIdx.y;
    int tid = threadIdx.x;
    int c   = tid;

    __shared__ float t_s[C_];
    __shared__ float hpart[4][CH];
    __shared__ float h_s[CH];

    cudaGridDependencySynchronize();   // pool completed -> writes visible

    t_s[c] = (pos < 9) ? g_pooled[(b * C_ + c) * 9 + pos] : g_gmean[b * C_ + c];
    __syncthreads();

    {
        int o = tid & 63, part = tid >> 6;
        const float* wt = g_w1t + part * 64 * CH + o;
        const float* ts = t_s + part * 64;
        float acc = 0.f;
        #pragma unroll 8
        for (int k = 0; k < 64; k++) acc = fmaf(wt[k * CH], ts[k], acc);
        hpart[part][o] = acc;
    }
    __syncthreads();
    if (tid < CH) {
        float h = hpart[0][tid] + hpart[1][tid] + hpart[2][tid] + hpart[3][tid] + b1[tid];
        h = (h - bn_m[tid]) * (bn_g[tid] * rsqrtf(bn_v[tid] + 1e-5f)) + bn_b[tid];
        h = 0.5f * h * (1.0f + erff(h * 0.70710678118654752f));
        h_s[tid] = h;
    }
    __syncthreads();

    float v[G_];
    #pragma unroll
    for (int g = 0; g < G_; g++) v[g] = b2[g * C_ + c];
    #pragma unroll 8
    for (int k = 0; k < CH; k++) {
        float h = h_s[k];
        const float* row = g_w2t + (size_t)k * (C_ * G_) + c;
        #pragma unroll
        for (int g = 0; g < G_; g++) v[g] = fmaf(row[g * C_], h, v[g]);
    }
    float m = fmaxf(fmaxf(v[0], v[1]), fmaxf(v[2], v[3]));
    float e[G_]; float s = 0.f;
    #pragma unroll
    for (int g = 0; g < G_; g++) { e[g] = expf(v[g] - m); s += e[g]; }
    float inv = 1.f / s;

    if (pos < 9) {
        float w = 0.f;
        #pragma unroll
        for (int g = 0; g < G_; g++) w = fmaf(e[g] * inv, w_k[(g * C_ + c) * 9 + pos], w);
        g_weight[(b * C_ + c) * 9 + pos] = w;
    } else {
        float bb = 0.f;
        #pragma unroll
        for (int g = 0; g < G_; g++) bb = fmaf(e[g] * inv, b_k[g * C_ + c], bb);
        g_bias[b * C_ + c] = bb;
    }
}

// ---------------------------------------------------------------------------
// Kernel 3: depthwise 3x3 conv. Reversed plane order for L2 reuse; STREAMING
// loads (__ldcs) so demand fills don't displace the unconsumed pool window;
// streaming stores (__stcs) so output doesn't either. Full x prefetch
// before the PDL sync. 288 thr = 12 row-groups x 24 col-groups.
// ---------------------------------------------------------------------------
__device__ __forceinline__ void ld_row(const float* __restrict__ xp, int ir, int c0,
                                       float& l, float4& m, float& r)
{
    if (ir >= 0 && ir < H_) {
        const float* row = xp + ir * W_;
        m = __ldcs(reinterpret_cast<const float4*>(row + c0));
        l = (c0 > 0)  ? __ldcs(row + c0 - 1) : 0.f;
        r = (c0 < 92) ? __ldcs(row + c0 + 4) : 0.f;
    } else {
        m = make_float4(0.f, 0.f, 0.f, 0.f);
        l = 0.f; r = 0.f;
    }
}

__global__ __launch_bounds__(288, 2) void conv_kernel(const float* __restrict__ x,
                                                      float* __restrict__ out)
{
    int bc  = BC - 1 - blockIdx.x;   // reverse order for L2 reuse of pool's tail
    int tid = threadIdx.x;
    int r_g = tid / 24;              // 0..11
    int c0  = (tid % 24) * 4;        // 0..92
    const float* xp = x + (size_t)bc * PLANE;
    int rbase = r_g * 8;

    // ---- prefetch ALL rows (weight-independent, x is a graph input) ----
    float  l[10], r[10];
    float4 m[10];
    #pragma unroll
    for (int i = 0; i < 10; i++)
        ld_row(xp, rbase - 1 + i, c0, l[i], m[i], r[i]);

    cudaGridDependencySynchronize();   // proj completed -> weights visible

    float w[9];
    #pragma unroll
    for (int i = 0; i < 9; i++) w[i] = __ldg(&g_weight[bc * 9 + i]);
    float bb = __ldg(&g_bias[bc]);

    float* op = out + (size_t)bc * PLANE + (size_t)rbase * W_ + c0;

    #pragma unroll
    for (int i = 0; i < 8; i++) {
        float o0 = bb, o1 = bb, o2 = bb, o3 = bb;
        #pragma unroll
        for (int k = 0; k < 3; k++) {
            float w0 = w[k * 3 + 0], w1v = w[k * 3 + 1], w2v = w[k * 3 + 2];
            float  lv = l[i + k];
            float4 mv = m[i + k];
            float  rv = r[i + k];
            o0 = fmaf(w0, lv,   fmaf(w1v, mv.x, fmaf(w2v, mv.y, o0)));
            o1 = fmaf(w0, mv.x, fmaf(w1v, mv.y, fmaf(w2v, mv.z, o1)));
            o2 = fmaf(w0, mv.y, fmaf(w1v, mv.z, fmaf(w2v, mv.w, o2)));
            o3 = fmaf(w0, mv.z, fmaf(w1v, mv.w, fmaf(w2v, rv,   o3)));
        }
        __stcs(reinterpret_cast<float4*>(op + (size_t)i * W_),
               make_float4(o0, o1, o2, o3));
    }
}

// ---------------------------------------------------------------------------
// Launch. PDL with completion ordering (proven correct).
// ---------------------------------------------------------------------------
extern "C" void kernel_launch(void* const* d_in, const int* in_sizes, int n_in,
                              void* d_out, int out_size)
{
    const float* x    = (const float*)d_in[0];
    const float* w_k  = (const float*)d_in[1];
    const float* b_k  = (const float*)d_in[2];
    const float* w1   = (const float*)d_in[3];
    const float* b1   = (const float*)d_in[4];
    const float* bn_g = (const float*)d_in[5];
    const float* bn_b = (const float*)d_in[6];
    const float* bn_m = (const float*)d_in[7];
    const float* bn_v = (const float*)d_in[8];
    const float* w2   = (const float*)d_in[9];
    const float* b2   = (const float*)d_in[10];
    float* out = (float*)d_out;

    pool_kernel<<<BC + 80, 288>>>(x, w1, w2);

    cudaLaunchAttribute attr[1];
    attr[0].id = cudaLaunchAttributeProgrammaticStreamSerialization;
    attr[0].val.programmaticStreamSerializationAllowed = 1;

    {
        cudaLaunchConfig_t cfg = {};
        cfg.gridDim  = dim3(10, B_);
        cfg.blockDim = dim3(256);
        cfg.dynamicSmemBytes = 0;
        cfg.stream = 0;
        cfg.attrs = attr;
        cfg.numAttrs = 1;
        cudaLaunchKernelEx(&cfg, proj_kernel,
                           b1, bn_g, bn_b, bn_m, bn_v, b2, w_k, b_k);
    }
    {
        cudaLaunchConfig_t cfg = {};
        cfg.gridDim  = dim3(BC);
        cfg.blockDim = dim3(288);
        cfg.dynamicSmemBytes = 0;
        cfg.stream = 0;
        cfg.attrs = attr;
        cfg.numAttrs = 1;
        cudaLaunchKernelEx(&cfg, conv_kernel, x, out);
    }
}

// round 15
// speedup vs baseline: 1.0709x; 1.0709x over previous
#include <cuda_runtime.h>
#include <math.h>

#define B_  16
#define C_  256
#define H_  96
#define W_  96
#define G_  4
#define KK  3
#define RED 4
#define CH  (C_ / RED)        // 64
#define PLANE (H_ * W_)       // 9216
#define BC (B_ * C_)          // 4096

// Scratch (allocation-free rule -> __device__ globals)
__device__ float g_pooled[B_ * C_ * 9];
__device__ float g_gmean [B_ * C_];
__device__ float g_weight[B_ * C_ * 9];
__device__ float g_bias  [B_ * C_];
__device__ float g_w1t[C_ * CH];          // w1t[k][o] = w1[o][k]      (256 x 64)
__device__ float g_w2t2[CH * C_ * G_];    // w2t2[k][c][g] = w2[g*C+c][k] (64 x 256 x 4)

// ---------------------------------------------------------------------------
// Kernel 1: pool (blocks 0..4095): 9 warps, one warp per 32x32 pooling block.
// Blocks 4096..4175: weight transpose (w2 repacked to [k][c][g] for float4
// loads in proj).
// ---------------------------------------------------------------------------
__global__ __launch_bounds__(288) void pool_kernel(const float* __restrict__ x,
                                                   const float* __restrict__ w1,
                                                   const float* __restrict__ w2)
{
    int tid = threadIdx.x;
    if (blockIdx.x >= BC) {
        int idx = (blockIdx.x - BC) * 288 + tid;
        if (idx < C_ * CH) {
            int k = idx / CH, o = idx % CH;
            g_w1t[idx] = w1[o * C_ + k];
        }
        for (int i = idx; i < CH * C_ * G_; i += 80 * 288) {
            int k = i / (C_ * G_);
            int rem = i % (C_ * G_);
            int c = rem / G_, g = rem % G_;
            g_w2t2[i] = w2[(size_t)(g * C_ + c) * CH + k];
        }
        return;
    }

    int bc = blockIdx.x;
    const float4* xp = reinterpret_cast<const float4*>(x + (size_t)bc * PLANE);
    __shared__ float bins[9];
    int wid = tid >> 5, lane = tid & 31;
    int br = wid / 3, cb = wid % 3;   // pooling block (row, col)

    float a = 0.f;
    #pragma unroll
    for (int j = 0; j < 8; j++) {
        int idx = j * 32 + lane;
        int r = idx >> 3, c = idx & 7;           // 8 float4 per block row
        float4 v = xp[(br * 32 + r) * 24 + cb * 8 + c];
        a += (v.x + v.y) + (v.z + v.w);
    }
    #pragma unroll
    for (int o = 16; o > 0; o >>= 1) a += __shfl_down_sync(0xffffffffu, a, o);
    if (lane == 0) bins[wid] = a;
    __syncthreads();

    if (tid < 9) g_pooled[bc * 9 + tid] = bins[tid] * (1.f / 1024.f);
    if (tid == 0) {
        float t = 0.f;
        #pragma unroll
        for (int i = 0; i < 9; i++) t += bins[i];
        g_gmean[bc] = t * (1.f / (float)PLANE);
    }
}

// ---------------------------------------------------------------------------
// Kernel 2: proj + softmax + mixdown. w2 stage uses float4 loads on the
// [k][c][g] packed layout: 1 LDG.128 + 4 FMA per k per thread.
// ---------------------------------------------------------------------------
__global__ __launch_bounds__(256) void proj_kernel(
    const float* __restrict__ b1,
    const float* __restrict__ bn_g, const float* __restrict__ bn_b,
    const float* __restrict__ bn_m, const float* __restrict__ bn_v,
    const float* __restrict__ b2,
    const float* __restrict__ w_k, const float* __restrict__ b_k)
{
    int pos = blockIdx.x;
    int b   = blockIdx.y;
    int tid = threadIdx.x;
    int c   = tid;

    __shared__ float t_s[C_];
    __shared__ float hpart[4][CH];
    __shared__ float h_s[CH];

    cudaGridDependencySynchronize();   // pool completed -> writes visible

    t_s[c] = (pos < 9) ? g_pooled[(b * C_ + c) * 9 + pos] : g_gmean[b * C_ + c];
    __syncthreads();

    {
        int o = tid & 63, part = tid >> 6;
        const float* wt = g_w1t + part * 64 * CH + o;
        const float* ts = t_s + part * 64;
        float acc = 0.f;
        #pragma unroll 8
        for (int k = 0; k < 64; k++) acc = fmaf(wt[k * CH], ts[k], acc);
        hpart[part][o] = acc;
    }
    __syncthreads();
    if (tid < CH) {
        float h = hpart[0][tid] + hpart[1][tid] + hpart[2][tid] + hpart[3][tid] + b1[tid];
        h = (h - bn_m[tid]) * (bn_g[tid] * rsqrtf(bn_v[tid] + 1e-5f)) + bn_b[tid];
        h = 0.5f * h * (1.0f + erff(h * 0.70710678118654752f));
        h_s[tid] = h;
    }
    __syncthreads();

    float v0 = 0.f, v1 = 0.f, v2 = 0.f, v3 = 0.f;
    const float4* wrow = reinterpret_cast<const float4*>(g_w2t2) + c;  // [k][c] float4
    #pragma unroll 8
    for (int k = 0; k < CH; k++) {
        float h = h_s[k];
        float4 wv = wrow[k * C_];
        v0 = fmaf(wv.x, h, v0);
        v1 = fmaf(wv.y, h, v1);
        v2 = fmaf(wv.z, h, v2);
        v3 = fmaf(wv.w, h, v3);
    }
    float v[G_];
    v[0] = v0 + b2[0 * C_ + c];
    v[1] = v1 + b2[1 * C_ + c];
    v[2] = v2 + b2[2 * C_ + c];
    v[3] = v3 + b2[3 * C_ + c];

    float m = fmaxf(fmaxf(v[0], v[1]), fmaxf(v[2], v[3]));
    float e[G_]; float s = 0.f;
    #pragma unroll
    for (int g = 0; g < G_; g++) { e[g] = expf(v[g] - m); s += e[g]; }
    float inv = 1.f / s;

    if (pos < 9) {
        float w = 0.f;
        #pragma unroll
        for (int g = 0; g < G_; g++) w = fmaf(e[g] * inv, w_k[(g * C_ + c) * 9 + pos], w);
        g_weight[(b * C_ + c) * 9 + pos] = w;
    } else {
        float bb = 0.f;
        #pragma unroll
        for (int g = 0; g < G_; g++) bb = fmaf(e[g] * inv, b_k[g * C_ + c], bb);
        g_bias[b * C_ + c] = bb;
    }
}

// ---------------------------------------------------------------------------
// Kernel 3: depthwise 3x3 conv (R13 proven form). Reversed plane order for
// L2 reuse of pool's tail; NORMAL loads (seed/halo reuse intact), streaming
// stores (__stcs). Full x prefetch before the PDL sync.
// 288 threads = 12 row-groups (8 rows) x 24 col-groups (4 cols).
// ---------------------------------------------------------------------------
__device__ __forceinline__ void ld_row(const float* __restrict__ xp, int ir, int c0,
                                       float& l, float4& m, float& r)
{
    if (ir >= 0 && ir < H_) {
        const float* row = xp + ir * W_;
        m = *reinterpret_cast<const float4*>(row + c0);
        l = (c0 > 0)  ? __ldg(row + c0 - 1) : 0.f;
        r = (c0 < 92) ? __ldg(row + c0 + 4) : 0.f;
    } else {
        m = make_float4(0.f, 0.f, 0.f, 0.f);
        l = 0.f; r = 0.f;
    }
}

__global__ __launch_bounds__(288, 2) void conv_kernel(const float* __restrict__ x,
                                                      float* __restrict__ out)
{
    int bc  = BC - 1 - blockIdx.x;   // reverse order for L2 reuse of pool's tail
    int tid = threadIdx.x;
    int r_g = tid / 24;              // 0..11
    int c0  = (tid % 24) * 4;        // 0..92
    const float* xp = x + (size_t)bc * PLANE;
    int rbase = r_g * 8;

    // ---- prefetch ALL rows (weight-independent, x is a graph input) ----
    float  l[10], r[10];
    float4 m[10];
    #pragma unroll
    for (int i = 0; i < 10; i++)
        ld_row(xp, rbase - 1 + i, c0, l[i], m[i], r[i]);

    cudaGridDependencySynchronize();   // proj completed -> weights visible

    float w[9];
    #pragma unroll
    for (int i = 0; i < 9; i++) w[i] = __ldg(&g_weight[bc * 9 + i]);
    float bb = __ldg(&g_bias[bc]);

    float* op = out + (size_t)bc * PLANE + (size_t)rbase * W_ + c0;

    #pragma unroll
    for (int i = 0; i < 8; i++) {
        float o0 = bb, o1 = bb, o2 = bb, o3 = bb;
        #pragma unroll
        for (int k = 0; k < 3; k++) {
            float w0 = w[k * 3 + 0], w1v = w[k * 3 + 1], w2v = w[k * 3 + 2];
            float  lv = l[i + k];
            float4 mv = m[i + k];
            float  rv = r[i + k];
            o0 = fmaf(w0, lv,   fmaf(w1v, mv.x, fmaf(w2v, mv.y, o0)));
            o1 = fmaf(w0, mv.x, fmaf(w1v, mv.y, fmaf(w2v, mv.z, o1)));
            o2 = fmaf(w0, mv.y, fmaf(w1v, mv.z, fmaf(w2v, mv.w, o2)));
            o3 = fmaf(w0, mv.z, fmaf(w1v, mv.w, fmaf(w2v, rv,   o3)));
        }
        __stcs(reinterpret_cast<float4*>(op + (size_t)i * W_),
               make_float4(o0, o1, o2, o3));
    }
}

// ---------------------------------------------------------------------------
// Launch. PDL with completion ordering (proven correct).
// ---------------------------------------------------------------------------
extern "C" void kernel_launch(void* const* d_in, const int* in_sizes, int n_in,
                              void* d_out, int out_size)
{
    const float* x    = (const float*)d_in[0];
    const float* w_k  = (const float*)d_in[1];
    const float* b_k  = (const float*)d_in[2];
    const float* w1   = (const float*)d_in[3];
    const float* b1   = (const float*)d_in[4];
    const float* bn_g = (const float*)d_in[5];
    const float* bn_b = (const float*)d_in[6];
    const float* bn_m = (const float*)d_in[7];
    const float* bn_v = (const float*)d_in[8];
    const float* w2   = (const float*)d_in[9];
    const float* b2   = (const float*)d_in[10];
    float* out = (float*)d_out;

    pool_kernel<<<BC + 80, 288>>>(x, w1, w2);

    cudaLaunchAttribute attr[1];
    attr[0].id = cudaLaunchAttributeProgrammaticStreamSerialization;
    attr[0].val.programmaticStreamSerializationAllowed = 1;

    {
        cudaLaunchConfig_t cfg = {};
        cfg.gridDim  = dim3(10, B_);
        cfg.blockDim = dim3(256);
        cfg.dynamicSmemBytes = 0;
        cfg.stream = 0;
        cfg.attrs = attr;
        cfg.numAttrs = 1;
        cudaLaunchKernelEx(&cfg, proj_kernel,
                           b1, bn_g, bn_b, bn_m, bn_v, b2, w_k, b_k);
    }
    {
        cudaLaunchConfig_t cfg = {};
        cfg.gridDim  = dim3(BC);
        cfg.blockDim = dim3(288);
        cfg.dynamicSmemBytes = 0;
        cfg.stream = 0;
        cfg.attrs = attr;
        cfg.numAttrs = 1;
        cudaLaunchKernelEx(&cfg, conv_kernel, x, out);
    }
}